// round 12
// baseline (speedup 1.0000x reference)
#include <cuda_runtime.h>
#include <cuda_fp16.h>
#include <cstdint>
#include <math.h>

#define NN 100000
#define EE 1600000

// Scratch (device globals — no allocations allowed)
__device__ __align__(256) __half g_sup16[NN * 64];   // fp16 support (all layers)
__device__ __align__(256) __half g_h16[NN * 64];     // fp16 hidden state
__device__ __align__(256) int    g_cnt[NN + 1];      // counts -> row offsets
__device__ __align__(256) int    g_cur[NN];          // fill cursors
__device__ __align__(256) int2   g_edge[EE];         // CSR payload: (src, w bits)
__device__ __align__(256) int    g_blksum[256];      // scan partials

// ---------------------------------------------------------------------------
// CSR build: histogram -> scan (2 kernels) -> fill
// Grid-stride ILP-4 in hist/fill: coalesced lanes, 4 independent atomics/thread.
// ---------------------------------------------------------------------------
__global__ __launch_bounds__(256) void hist_kernel(
    const int* __restrict__ tgt, int* __restrict__ cnt, int E, int stride)
{
    const int gid = blockIdx.x * 256 + threadIdx.x;
    int t[4];
    #pragma unroll
    for (int k = 0; k < 4; k++) {
        const int e = gid + k * stride;
        t[k] = (e < E) ? tgt[e] : -1;
    }
    #pragma unroll
    for (int k = 0; k < 4; k++)
        if (t[k] >= 0) atomicAdd(&cnt[t[k] + 1], 1);
}

__global__ __launch_bounds__(1024) void scan1_kernel(
    int* __restrict__ data, int n, int* __restrict__ blksum)
{
    __shared__ int wsum[32];
    const int tid = threadIdx.x;
    const int lane = tid & 31;
    const int warp = tid >> 5;
    const int i = blockIdx.x * 1024 + tid;
    int v = (i < n) ? data[i] : 0;
    #pragma unroll
    for (int off = 1; off < 32; off <<= 1) {
        int t = __shfl_up_sync(0xFFFFFFFFu, v, off);
        if (lane >= off) v += t;
    }
    if (lane == 31) wsum[warp] = v;
    __syncthreads();
    if (warp == 0) {
        int s = wsum[lane];
        #pragma unroll
        for (int off = 1; off < 32; off <<= 1) {
            int t = __shfl_up_sync(0xFFFFFFFFu, s, off);
            if (lane >= off) s += t;
        }
        wsum[lane] = s;
    }
    __syncthreads();
    if (warp > 0) v += wsum[warp - 1];
    if (i < n) data[i] = v;
    if (tid == 1023) blksum[blockIdx.x] = v;
}

// scan2 merged into scan3: every block re-scans blksum[0..nb) itself.
__global__ __launch_bounds__(1024) void scan23_kernel(
    int* __restrict__ data, int n, const int* __restrict__ blksum,
    int* __restrict__ cur, int nnodes, int nb)
{
    __shared__ int pref[128];
    const int tid = threadIdx.x;
    if (tid < 128) pref[tid] = (tid < nb) ? blksum[tid] : 0;
    __syncthreads();
    #pragma unroll
    for (int off = 1; off < 128; off <<= 1) {
        int t = 0;
        if (tid < 128 && tid >= off) t = pref[tid - off];
        __syncthreads();
        if (tid < 128) pref[tid] += t;
        __syncthreads();
    }
    const int add = (blockIdx.x > 0) ? pref[blockIdx.x - 1] : 0;
    const int i = blockIdx.x * 1024 + tid;
    if (i >= n) return;
    const int v = data[i] + add;
    data[i] = v;
    if (i < nnodes) cur[i] = v;
}

__global__ __launch_bounds__(256) void fill_kernel(
    const int* __restrict__ src, const int* __restrict__ tgt,
    const float* __restrict__ w, int* __restrict__ cur,
    int2* __restrict__ edges, int E, int stride)
{
    const int gid = blockIdx.x * 256 + threadIdx.x;
    int t[4];
    #pragma unroll
    for (int k = 0; k < 4; k++) {
        const int e = gid + k * stride;
        t[k] = (e < E) ? tgt[e] : -1;
    }
    int pos[4];
    #pragma unroll
    for (int k = 0; k < 4; k++)
        if (t[k] >= 0) pos[k] = atomicAdd(&cur[t[k]], 1);
    #pragma unroll
    for (int k = 0; k < 4; k++) {
        const int e = gid + k * stride;
        if (t[k] >= 0)
            edges[pos[k]] = make_int2(src[e], __float_as_int(w[e]));
    }
}

// ---------------------------------------------------------------------------
// HMMA GEMM: C16[M,OUTC] = A[M,K] @ W[K,OUTC]  (fp16 in, fp32 accum, fp16 out)
// Tile: BM=128, BN=64, BK=64. 256 threads = 8 warps (4m x 2n), warp = 32x32.
// ---------------------------------------------------------------------------
#define SMEM_STRIDE 72   // halves per row (144 B) -> conflict-free LDSM

__device__ __forceinline__ unsigned smem_u32(const void* p) {
    return (unsigned)__cvta_generic_to_shared(p);
}

__device__ __forceinline__ void ldsm_x4(unsigned& r0, unsigned& r1,
                                        unsigned& r2, unsigned& r3, unsigned a) {
    asm volatile("ldmatrix.sync.aligned.m8n8.x4.shared.b16 {%0,%1,%2,%3}, [%4];"
                 : "=r"(r0), "=r"(r1), "=r"(r2), "=r"(r3) : "r"(a));
}
__device__ __forceinline__ void ldsm_x4_t(unsigned& r0, unsigned& r1,
                                          unsigned& r2, unsigned& r3, unsigned a) {
    asm volatile("ldmatrix.sync.aligned.m8n8.x4.trans.shared.b16 {%0,%1,%2,%3}, [%4];"
                 : "=r"(r0), "=r"(r1), "=r"(r2), "=r"(r3) : "r"(a));
}
__device__ __forceinline__ void mma16816(float c[4], const unsigned a[4],
                                         unsigned b0, unsigned b1) {
    asm volatile(
        "mma.sync.aligned.m16n8k16.row.col.f32.f16.f16.f32 "
        "{%0,%1,%2,%3}, {%4,%5,%6,%7}, {%8,%9}, {%0,%1,%2,%3};"
        : "+f"(c[0]), "+f"(c[1]), "+f"(c[2]), "+f"(c[3])
        : "r"(a[0]), "r"(a[1]), "r"(a[2]), "r"(a[3]), "r"(b0), "r"(b1));
}

template <int K, int OUTC, bool A_FP32>
__global__ __launch_bounds__(256) void hgemm_kernel(
    const float* __restrict__ A32, const __half* __restrict__ A16,
    const float* __restrict__ W, __half* __restrict__ C16, int M)
{
    __shared__ __half a_s[128 * SMEM_STRIDE];
    __shared__ __half b_s[64 * SMEM_STRIDE];

    const int tid = threadIdx.x;
    const int lane = tid & 31;
    const int wid = tid >> 5;
    const int wm = (wid >> 1) * 32;
    const int wn = (wid & 1) * 32;
    const int row0 = blockIdx.x * 128;

    float c[2][4][4] = {};

    for (int k0 = 0; k0 < K; k0 += 64) {
        // ---- B tile first ----
        #pragma unroll
        for (int p = 0; p < 4; p++) {
            const int idx = tid + p * 256;
            const int row = idx >> 4;
            const int ch = idx & 15;
            uint2 st = make_uint2(0u, 0u);
            if (OUTC == 64 || ch * 4 < OUTC) {
                const float4 v = *(const float4*)&W[(size_t)(k0 + row) * OUTC + ch * 4];
                __half2 h0 = __floats2half2_rn(v.x, v.y);
                __half2 h1 = __floats2half2_rn(v.z, v.w);
                st.x = *(const unsigned*)&h0;
                st.y = *(const unsigned*)&h1;
            }
            *(uint2*)&b_s[row * SMEM_STRIDE + ch * 4] = st;
        }
        // ---- A tile ----
        if (A_FP32) {
            #pragma unroll
            for (int half = 0; half < 2; half++) {
                float4 vals[4];
                #pragma unroll
                for (int q = 0; q < 4; q++) {
                    const int idx = tid + (half * 4 + q) * 256;
                    const int row = idx >> 4;
                    const int ch = idx & 15;
                    const int grow = row0 + row;
                    vals[q] = make_float4(0.f, 0.f, 0.f, 0.f);
                    if (grow < M)
                        vals[q] = *(const float4*)&A32[(size_t)grow * K + k0 + ch * 4];
                }
                #pragma unroll
                for (int q = 0; q < 4; q++) {
                    const int idx = tid + (half * 4 + q) * 256;
                    const int row = idx >> 4;
                    const int ch = idx & 15;
                    __half2 h0 = __floats2half2_rn(vals[q].x, vals[q].y);
                    __half2 h1 = __floats2half2_rn(vals[q].z, vals[q].w);
                    uint2 st;
                    st.x = *(const unsigned*)&h0;
                    st.y = *(const unsigned*)&h1;
                    *(uint2*)&a_s[row * SMEM_STRIDE + ch * 4] = st;
                }
            }
        } else {
            #pragma unroll
            for (int p = 0; p < 4; p++) {
                const int idx = tid + p * 256;
                const int row = idx >> 3;
                const int ch = idx & 7;
                const int grow = row0 + row;
                uint4 v = make_uint4(0u, 0u, 0u, 0u);
                if (grow < M) v = *(const uint4*)&A16[(size_t)grow * K + k0 + ch * 8];
                *(uint4*)&a_s[row * SMEM_STRIDE + ch * 8] = v;
            }
        }
        __syncthreads();

        #pragma unroll
        for (int ks = 0; ks < 4; ks++) {
            const int k = ks * 16;
            unsigned a[2][4];
            #pragma unroll
            for (int mt = 0; mt < 2; mt++) {
                const int r = wm + mt * 16 + (lane & 15);
                const int cc = k + (lane >> 4) * 8;
                ldsm_x4(a[mt][0], a[mt][1], a[mt][2], a[mt][3],
                        smem_u32(&a_s[r * SMEM_STRIDE + cc]));
            }
            unsigned b[2][4];
            #pragma unroll
            for (int nt2 = 0; nt2 < 2; nt2++) {
                const int kr = k + (lane & 15);
                const int nc = wn + nt2 * 16 + (lane >> 4) * 8;
                ldsm_x4_t(b[nt2][0], b[nt2][1], b[nt2][2], b[nt2][3],
                          smem_u32(&b_s[kr * SMEM_STRIDE + nc]));
            }
            #pragma unroll
            for (int mt = 0; mt < 2; mt++)
                #pragma unroll
                for (int nt = 0; nt < 4; nt++)
                    mma16816(c[mt][nt], a[mt],
                             b[nt >> 1][(nt & 1) * 2], b[nt >> 1][(nt & 1) * 2 + 1]);
        }
        if (K > 64) __syncthreads();
    }

    #pragma unroll
    for (int mt = 0; mt < 2; mt++) {
        #pragma unroll
        for (int nt = 0; nt < 4; nt++) {
            const int col = wn + nt * 8 + (lane & 3) * 2;
            if (OUTC == 64 || col < OUTC) {
                const int r0 = row0 + wm + mt * 16 + (lane >> 2);
                if (r0 < M) {
                    __half2 v = __floats2half2_rn(c[mt][nt][0], c[mt][nt][1]);
                    *(__half2*)&C16[(size_t)r0 * OUTC + col] = v;
                }
                const int r1 = r0 + 8;
                if (r1 < M) {
                    __half2 v = __floats2half2_rn(c[mt][nt][2], c[mt][nt][3]);
                    *(__half2*)&C16[(size_t)r1 * OUTC + col] = v;
                }
            }
        }
    }
}

// ---------------------------------------------------------------------------
// fp16 CSR aggregate (COLS=64) + fused epilogue. 8 threads/node, 8 halves each.
// MODE 0: h16 = relu(agg+b);  MODE 1: h16 = relu(agg+b) + h16
// ---------------------------------------------------------------------------
__device__ __forceinline__ void acc_edge16(
    float acc[8], const __half* __restrict__ sup, int s, float w, int lane)
{
    const uint4 raw = *(const uint4*)(sup + (size_t)s * 64 + lane * 8);
    const __half2* hp = (const __half2*)&raw;
    #pragma unroll
    for (int p = 0; p < 4; p++) {
        const float2 f = __half22float2(hp[p]);
        acc[p * 2 + 0] += f.x * w;
        acc[p * 2 + 1] += f.y * w;
    }
}

template <int MODE>
__global__ __launch_bounds__(256) void csr_agg16_kernel(
    const __half* __restrict__ sup, const int* __restrict__ row_off,
    const int2* __restrict__ edges, const float* __restrict__ bias,
    __half* __restrict__ h16, int M)
{
    const int gid = blockIdx.x * 256 + threadIdx.x;
    const int node = gid >> 3;
    const int lane = gid & 7;
    if (node >= M) return;

    const int beg = row_off[node];
    const int end = row_off[node + 1];

    float acc[8] = {};
    int j = beg;
    for (; j + 1 < end; j += 2) {
        const int2 e0 = edges[j];
        const int2 e1 = edges[j + 1];
        acc_edge16(acc, sup, e0.x, __int_as_float(e0.y), lane);
        acc_edge16(acc, sup, e1.x, __int_as_float(e1.y), lane);
    }
    if (j < end) {
        const int2 e0 = edges[j];
        acc_edge16(acc, sup, e0.x, __int_as_float(e0.y), lane);
    }

    const float4 b0 = ((const float4*)bias)[lane * 2];
    const float4 b1 = ((const float4*)bias)[lane * 2 + 1];
    const float bb[8] = {b0.x, b0.y, b0.z, b0.w, b1.x, b1.y, b1.z, b1.w};
    float res[8];
    #pragma unroll
    for (int p = 0; p < 8; p++) res[p] = fmaxf(acc[p] + bb[p], 0.f);

    __half* hp = h16 + (size_t)node * 64 + lane * 8;
    if (MODE == 1) {
        const uint4 rraw = *(const uint4*)hp;
        const __half2* rh = (const __half2*)&rraw;
        #pragma unroll
        for (int p = 0; p < 4; p++) {
            const float2 f = __half22float2(rh[p]);
            res[p * 2 + 0] += f.x;
            res[p * 2 + 1] += f.y;
        }
    }

    uint4 st;
    __half2 q0 = __floats2half2_rn(res[0], res[1]);
    __half2 q1 = __floats2half2_rn(res[2], res[3]);
    __half2 q2 = __floats2half2_rn(res[4], res[5]);
    __half2 q3 = __floats2half2_rn(res[6], res[7]);
    st.x = *(const unsigned*)&q0; st.y = *(const unsigned*)&q1;
    st.z = *(const unsigned*)&q2; st.w = *(const unsigned*)&q3;
    *(uint4*)hp = st;
}

// ---------------------------------------------------------------------------
// fp16 CSR aggregate, COLS=40, fused log_softmax (final layer).
// 16 threads/node; lanes 0-9 hold 4 halves (uint2) each.
// ---------------------------------------------------------------------------
__global__ __launch_bounds__(256) void csr_agg40_final_kernel(
    const __half* __restrict__ sup, const int* __restrict__ row_off,
    const int2* __restrict__ edges, const float* __restrict__ bias,
    float* __restrict__ out, int M)
{
    const int gid = blockIdx.x * 256 + threadIdx.x;
    const int node = gid >> 4;
    const int lane = gid & 15;
    if (node >= M) return;

    const bool active = (lane < 10);
    float a0 = 0.f, a1 = 0.f, a2 = 0.f, a3 = 0.f;

    if (active) {
        const int beg = row_off[node];
        const int end = row_off[node + 1];
        for (int j = beg; j < end; j++) {
            const int2 e = edges[j];
            const float w = __int_as_float(e.y);
            const uint2 raw = *(const uint2*)(sup + (size_t)e.x * 40 + lane * 4);
            const __half2* hp = (const __half2*)&raw;
            const float2 f0 = __half22float2(hp[0]);
            const float2 f1 = __half22float2(hp[1]);
            a0 += f0.x * w; a1 += f0.y * w;
            a2 += f1.x * w; a3 += f1.y * w;
        }
    }

    float m = -INFINITY;
    if (active) {
        const float* b = bias + lane * 4;
        a0 += b[0]; a1 += b[1]; a2 += b[2]; a3 += b[3];
        m = fmaxf(fmaxf(a0, a1), fmaxf(a2, a3));
    }
    #pragma unroll
    for (int off = 8; off > 0; off >>= 1)
        m = fmaxf(m, __shfl_xor_sync(0xFFFFFFFFu, m, off));
    float s = 0.f;
    if (active)
        s = expf(a0 - m) + expf(a1 - m) + expf(a2 - m) + expf(a3 - m);
    #pragma unroll
    for (int off = 8; off > 0; off >>= 1)
        s += __shfl_xor_sync(0xFFFFFFFFu, s, off);
    const float lse = m + logf(s);
    if (active) {
        float* o = out + (size_t)node * 40 + lane * 4;
        o[0] = a0 - lse; o[1] = a1 - lse; o[2] = a2 - lse; o[3] = a3 - lse;
    }
}

// ---------------------------------------------------------------------------
// Launch (single stream)
// ---------------------------------------------------------------------------
extern "C" void kernel_launch(void* const* d_in, const int* in_sizes, int n_in,
                              void* d_out, int out_size)
{
    const float* x   = (const float*)d_in[0];
    const int*   src = (const int*)d_in[1];
    const int*   tgt = (const int*)d_in[2];
    const float* mw  = (const float*)d_in[3];
    const float* W0  = (const float*)d_in[4];
    const float* b0  = (const float*)d_in[5];
    const float* W1  = (const float*)d_in[6];
    const float* b1  = (const float*)d_in[7];
    const float* W2  = (const float*)d_in[8];
    const float* b2  = (const float*)d_in[9];
    const float* W3  = (const float*)d_in[10];
    const float* b3  = (const float*)d_in[11];
    float* out = (float*)d_out;

    const int M = NN;
    const int E = in_sizes[1];

    __half *sup16, *h16;
    int *cnt, *cur, *blksum;
    int2 *edges;
    cudaGetSymbolAddress((void**)&sup16, g_sup16);
    cudaGetSymbolAddress((void**)&h16, g_h16);
    cudaGetSymbolAddress((void**)&cnt, g_cnt);
    cudaGetSymbolAddress((void**)&cur, g_cur);
    cudaGetSymbolAddress((void**)&blksum, g_blksum);
    cudaGetSymbolAddress((void**)&edges, g_edge);

    const int nscan = M + 1;
    const int scan_blocks = (nscan + 1023) / 1024;
    const int estride_blocks = (E + 1023) / 1024;     // ILP-4 grid-stride
    const int estride = estride_blocks * 256;
    const int gemm_blocks = (M + 127) / 128;
    const int agg16_blocks = (M * 8 + 255) / 256;
    const int agg40_blocks = (M * 16 + 255) / 256;

    // ---- CSR build (by target) ----
    cudaMemsetAsync(cnt, 0, (size_t)nscan * sizeof(int));
    hist_kernel<<<estride_blocks, 256>>>(tgt, cnt, E, estride);
    scan1_kernel<<<scan_blocks, 1024>>>(cnt, nscan, blksum);
    scan23_kernel<<<scan_blocks, 1024>>>(cnt, nscan, blksum, cur, M, scan_blocks);
    fill_kernel<<<estride_blocks, 256>>>(src, tgt, mw, cur, edges, E, estride);

    // ---- Layer 0: h = relu(agg(x@W0) + b0)
    hgemm_kernel<128, 64, true><<<gemm_blocks, 256>>>(x, (const __half*)0, W0, sup16, M);
    csr_agg16_kernel<0><<<agg16_blocks, 256>>>(sup16, cnt, edges, b0, h16, M);

    // ---- Layer 1: h = relu(agg(h@W1) + b1) + h
    hgemm_kernel<64, 64, false><<<gemm_blocks, 256>>>((const float*)0, h16, W1, sup16, M);
    csr_agg16_kernel<1><<<agg16_blocks, 256>>>(sup16, cnt, edges, b1, h16, M);

    // ---- Layer 2: h = relu(agg(h@W2) + b2) + h
    hgemm_kernel<64, 64, false><<<gemm_blocks, 256>>>((const float*)0, h16, W2, sup16, M);
    csr_agg16_kernel<1><<<agg16_blocks, 256>>>(sup16, cnt, edges, b2, h16, M);

    // ---- Layer 3: out = log_softmax(agg(h@W3) + b3)
    hgemm_kernel<64, 40, false><<<gemm_blocks, 256>>>((const float*)0, h16, W3, sup16, M);
    csr_agg40_final_kernel<<<agg40_blocks, 256>>>(sup16, cnt, edges, b3, out, M);
}

// round 13
// speedup vs baseline: 1.0334x; 1.0334x over previous
#include <cuda_runtime.h>
#include <cuda_fp16.h>
#include <cstdint>
#include <math.h>

#define NN 100000
#define EE 1600000

// Scratch (device globals — no allocations allowed; zero-initialized at load)
__device__ __align__(256) __half g_sup16[NN * 64];   // fp16 support (all layers)
__device__ __align__(256) __half g_h16[NN * 64];     // fp16 hidden state
__device__ __align__(256) int    g_hcnt[NN + 1];     // histogram (left zeroed each call)
__device__ __align__(256) int    g_row[NN + 1];      // row offsets (scan output)
__device__ __align__(256) int    g_rank[EE];         // per-edge within-target rank
__device__ __align__(256) int2   g_edge[EE];         // CSR payload: (src, w bits)
__device__ __align__(256) int    g_blksum[256];      // scan partials

// ---------------------------------------------------------------------------
// CSR build: hist_rank (one atomic pass, emits ranks) -> scan (2 kernels,
// re-zeroes hcnt) -> fill2 (atomic-free)
// ---------------------------------------------------------------------------
__global__ __launch_bounds__(256) void hist_rank_kernel(
    const int* __restrict__ tgt, int* __restrict__ hcnt,
    int* __restrict__ rank, int E)
{
    int e = blockIdx.x * 256 + threadIdx.x;
    if (e < E) rank[e] = atomicAdd(&hcnt[tgt[e] + 1], 1);
}

__global__ __launch_bounds__(1024) void scan1_kernel(
    const int* __restrict__ hcnt, int* __restrict__ row, int n,
    int* __restrict__ blksum)
{
    __shared__ int wsum[32];
    const int tid = threadIdx.x;
    const int lane = tid & 31;
    const int warp = tid >> 5;
    const int i = blockIdx.x * 1024 + tid;
    int v = (i < n) ? hcnt[i] : 0;
    #pragma unroll
    for (int off = 1; off < 32; off <<= 1) {
        int t = __shfl_up_sync(0xFFFFFFFFu, v, off);
        if (lane >= off) v += t;
    }
    if (lane == 31) wsum[warp] = v;
    __syncthreads();
    if (warp == 0) {
        int s = wsum[lane];
        #pragma unroll
        for (int off = 1; off < 32; off <<= 1) {
            int t = __shfl_up_sync(0xFFFFFFFFu, s, off);
            if (lane >= off) s += t;
        }
        wsum[lane] = s;
    }
    __syncthreads();
    if (warp > 0) v += wsum[warp - 1];
    if (i < n) row[i] = v;
    if (tid == 1023) blksum[blockIdx.x] = v;
}

// Adds block prefixes (each block re-scans blksum itself) and zeroes hcnt
// for the next replay.
__global__ __launch_bounds__(1024) void scan23_kernel(
    int* __restrict__ row, int* __restrict__ hcnt, int n,
    const int* __restrict__ blksum, int nb)
{
    __shared__ int pref[128];
    const int tid = threadIdx.x;
    if (tid < 128) pref[tid] = (tid < nb) ? blksum[tid] : 0;
    __syncthreads();
    #pragma unroll
    for (int off = 1; off < 128; off <<= 1) {
        int t = 0;
        if (tid < 128 && tid >= off) t = pref[tid - off];
        __syncthreads();
        if (tid < 128) pref[tid] += t;
        __syncthreads();
    }
    const int add = (blockIdx.x > 0) ? pref[blockIdx.x - 1] : 0;
    const int i = blockIdx.x * 1024 + tid;
    if (i >= n) return;
    row[i] += add;
    hcnt[i] = 0;   // restore invariant for next graph replay
}

// Atomic-free fill: position = row[tgt[e]] + rank[e].
__global__ __launch_bounds__(256) void fill2_kernel(
    const int* __restrict__ src, const int* __restrict__ tgt,
    const float* __restrict__ w, const int* __restrict__ row,
    const int* __restrict__ rank, int2* __restrict__ edges, int E)
{
    int e = blockIdx.x * 256 + threadIdx.x;
    if (e >= E) return;
    const int pos = row[tgt[e]] + rank[e];
    edges[pos] = make_int2(src[e], __float_as_int(w[e]));
}

// ---------------------------------------------------------------------------
// HMMA GEMM: C16[M,OUTC] = A[M,K] @ W[K,OUTC]  (fp16 in, fp32 accum, fp16 out)
// Tile: BM=128, BN=64, BK=64. 256 threads = 8 warps (4m x 2n), warp = 32x32.
// ---------------------------------------------------------------------------
#define SMEM_STRIDE 72   // halves per row (144 B) -> conflict-free LDSM

__device__ __forceinline__ unsigned smem_u32(const void* p) {
    return (unsigned)__cvta_generic_to_shared(p);
}

__device__ __forceinline__ void ldsm_x4(unsigned& r0, unsigned& r1,
                                        unsigned& r2, unsigned& r3, unsigned a) {
    asm volatile("ldmatrix.sync.aligned.m8n8.x4.shared.b16 {%0,%1,%2,%3}, [%4];"
                 : "=r"(r0), "=r"(r1), "=r"(r2), "=r"(r3) : "r"(a));
}
__device__ __forceinline__ void ldsm_x4_t(unsigned& r0, unsigned& r1,
                                          unsigned& r2, unsigned& r3, unsigned a) {
    asm volatile("ldmatrix.sync.aligned.m8n8.x4.trans.shared.b16 {%0,%1,%2,%3}, [%4];"
                 : "=r"(r0), "=r"(r1), "=r"(r2), "=r"(r3) : "r"(a));
}
__device__ __forceinline__ void mma16816(float c[4], const unsigned a[4],
                                         unsigned b0, unsigned b1) {
    asm volatile(
        "mma.sync.aligned.m16n8k16.row.col.f32.f16.f16.f32 "
        "{%0,%1,%2,%3}, {%4,%5,%6,%7}, {%8,%9}, {%0,%1,%2,%3};"
        : "+f"(c[0]), "+f"(c[1]), "+f"(c[2]), "+f"(c[3])
        : "r"(a[0]), "r"(a[1]), "r"(a[2]), "r"(a[3]), "r"(b0), "r"(b1));
}

template <int K, int OUTC, bool A_FP32>
__global__ __launch_bounds__(256) void hgemm_kernel(
    const float* __restrict__ A32, const __half* __restrict__ A16,
    const float* __restrict__ W, __half* __restrict__ C16, int M)
{
    __shared__ __half a_s[128 * SMEM_STRIDE];
    __shared__ __half b_s[64 * SMEM_STRIDE];

    const int tid = threadIdx.x;
    const int lane = tid & 31;
    const int wid = tid >> 5;
    const int wm = (wid >> 1) * 32;
    const int wn = (wid & 1) * 32;
    const int row0 = blockIdx.x * 128;

    float c[2][4][4] = {};

    for (int k0 = 0; k0 < K; k0 += 64) {
        // ---- B tile first ----
        #pragma unroll
        for (int p = 0; p < 4; p++) {
            const int idx = tid + p * 256;
            const int row = idx >> 4;
            const int ch = idx & 15;
            uint2 st = make_uint2(0u, 0u);
            if (OUTC == 64 || ch * 4 < OUTC) {
                const float4 v = *(const float4*)&W[(size_t)(k0 + row) * OUTC + ch * 4];
                __half2 h0 = __floats2half2_rn(v.x, v.y);
                __half2 h1 = __floats2half2_rn(v.z, v.w);
                st.x = *(const unsigned*)&h0;
                st.y = *(const unsigned*)&h1;
            }
            *(uint2*)&b_s[row * SMEM_STRIDE + ch * 4] = st;
        }
        // ---- A tile ----
        if (A_FP32) {
            #pragma unroll
            for (int half = 0; half < 2; half++) {
                float4 vals[4];
                #pragma unroll
                for (int q = 0; q < 4; q++) {
                    const int idx = tid + (half * 4 + q) * 256;
                    const int row = idx >> 4;
                    const int ch = idx & 15;
                    const int grow = row0 + row;
                    vals[q] = make_float4(0.f, 0.f, 0.f, 0.f);
                    if (grow < M)
                        vals[q] = *(const float4*)&A32[(size_t)grow * K + k0 + ch * 4];
                }
                #pragma unroll
                for (int q = 0; q < 4; q++) {
                    const int idx = tid + (half * 4 + q) * 256;
                    const int row = idx >> 4;
                    const int ch = idx & 15;
                    __half2 h0 = __floats2half2_rn(vals[q].x, vals[q].y);
                    __half2 h1 = __floats2half2_rn(vals[q].z, vals[q].w);
                    uint2 st;
                    st.x = *(const unsigned*)&h0;
                    st.y = *(const unsigned*)&h1;
                    *(uint2*)&a_s[row * SMEM_STRIDE + ch * 4] = st;
                }
            }
        } else {
            #pragma unroll
            for (int p = 0; p < 4; p++) {
                const int idx = tid + p * 256;
                const int row = idx >> 3;
                const int ch = idx & 7;
                const int grow = row0 + row;
                uint4 v = make_uint4(0u, 0u, 0u, 0u);
                if (grow < M) v = *(const uint4*)&A16[(size_t)grow * K + k0 + ch * 8];
                *(uint4*)&a_s[row * SMEM_STRIDE + ch * 8] = v;
            }
        }
        __syncthreads();

        #pragma unroll
        for (int ks = 0; ks < 4; ks++) {
            const int k = ks * 16;
            unsigned a[2][4];
            #pragma unroll
            for (int mt = 0; mt < 2; mt++) {
                const int r = wm + mt * 16 + (lane & 15);
                const int cc = k + (lane >> 4) * 8;
                ldsm_x4(a[mt][0], a[mt][1], a[mt][2], a[mt][3],
                        smem_u32(&a_s[r * SMEM_STRIDE + cc]));
            }
            unsigned b[2][4];
            #pragma unroll
            for (int nt2 = 0; nt2 < 2; nt2++) {
                const int kr = k + (lane & 15);
                const int nc = wn + nt2 * 16 + (lane >> 4) * 8;
                ldsm_x4_t(b[nt2][0], b[nt2][1], b[nt2][2], b[nt2][3],
                          smem_u32(&b_s[kr * SMEM_STRIDE + nc]));
            }
            #pragma unroll
            for (int mt = 0; mt < 2; mt++)
                #pragma unroll
                for (int nt = 0; nt < 4; nt++)
                    mma16816(c[mt][nt], a[mt],
                             b[nt >> 1][(nt & 1) * 2], b[nt >> 1][(nt & 1) * 2 + 1]);
        }
        if (K > 64) __syncthreads();
    }

    #pragma unroll
    for (int mt = 0; mt < 2; mt++) {
        #pragma unroll
        for (int nt = 0; nt < 4; nt++) {
            const int col = wn + nt * 8 + (lane & 3) * 2;
            if (OUTC == 64 || col < OUTC) {
                const int r0 = row0 + wm + mt * 16 + (lane >> 2);
                if (r0 < M) {
                    __half2 v = __floats2half2_rn(c[mt][nt][0], c[mt][nt][1]);
                    *(__half2*)&C16[(size_t)r0 * OUTC + col] = v;
                }
                const int r1 = r0 + 8;
                if (r1 < M) {
                    __half2 v = __floats2half2_rn(c[mt][nt][2], c[mt][nt][3]);
                    *(__half2*)&C16[(size_t)r1 * OUTC + col] = v;
                }
            }
        }
    }
}

// ---------------------------------------------------------------------------
// fp16 CSR aggregate (COLS=64) + fused epilogue. 8 threads/node, 8 halves each.
// MODE 0: h16 = relu(agg+b);  MODE 1: h16 = relu(agg+b) + h16
// ---------------------------------------------------------------------------
__device__ __forceinline__ void acc_edge16(
    float acc[8], const __half* __restrict__ sup, int s, float w, int lane)
{
    const uint4 raw = *(const uint4*)(sup + (size_t)s * 64 + lane * 8);
    const __half2* hp = (const __half2*)&raw;
    #pragma unroll
    for (int p = 0; p < 4; p++) {
        const float2 f = __half22float2(hp[p]);
        acc[p * 2 + 0] += f.x * w;
        acc[p * 2 + 1] += f.y * w;
    }
}

template <int MODE>
__global__ __launch_bounds__(256) void csr_agg16_kernel(
    const __half* __restrict__ sup, const int* __restrict__ row_off,
    const int2* __restrict__ edges, const float* __restrict__ bias,
    __half* __restrict__ h16, int M)
{
    const int gid = blockIdx.x * 256 + threadIdx.x;
    const int node = gid >> 3;
    const int lane = gid & 7;
    if (node >= M) return;

    const int beg = row_off[node];
    const int end = row_off[node + 1];

    float acc[8] = {};
    int j = beg;
    for (; j + 1 < end; j += 2) {
        const int2 e0 = edges[j];
        const int2 e1 = edges[j + 1];
        acc_edge16(acc, sup, e0.x, __int_as_float(e0.y), lane);
        acc_edge16(acc, sup, e1.x, __int_as_float(e1.y), lane);
    }
    if (j < end) {
        const int2 e0 = edges[j];
        acc_edge16(acc, sup, e0.x, __int_as_float(e0.y), lane);
    }

    const float4 b0 = ((const float4*)bias)[lane * 2];
    const float4 b1 = ((const float4*)bias)[lane * 2 + 1];
    const float bb[8] = {b0.x, b0.y, b0.z, b0.w, b1.x, b1.y, b1.z, b1.w};
    float res[8];
    #pragma unroll
    for (int p = 0; p < 8; p++) res[p] = fmaxf(acc[p] + bb[p], 0.f);

    __half* hp = h16 + (size_t)node * 64 + lane * 8;
    if (MODE == 1) {
        const uint4 rraw = *(const uint4*)hp;
        const __half2* rh = (const __half2*)&rraw;
        #pragma unroll
        for (int p = 0; p < 4; p++) {
            const float2 f = __half22float2(rh[p]);
            res[p * 2 + 0] += f.x;
            res[p * 2 + 1] += f.y;
        }
    }

    uint4 st;
    __half2 q0 = __floats2half2_rn(res[0], res[1]);
    __half2 q1 = __floats2half2_rn(res[2], res[3]);
    __half2 q2 = __floats2half2_rn(res[4], res[5]);
    __half2 q3 = __floats2half2_rn(res[6], res[7]);
    st.x = *(const unsigned*)&q0; st.y = *(const unsigned*)&q1;
    st.z = *(const unsigned*)&q2; st.w = *(const unsigned*)&q3;
    *(uint4*)hp = st;
}

// ---------------------------------------------------------------------------
// fp16 CSR aggregate, COLS=40, fused log_softmax (final layer).
// 16 threads/node; lanes 0-9 hold 4 halves (uint2) each.
// ---------------------------------------------------------------------------
__global__ __launch_bounds__(256) void csr_agg40_final_kernel(
    const __half* __restrict__ sup, const int* __restrict__ row_off,
    const int2* __restrict__ edges, const float* __restrict__ bias,
    float* __restrict__ out, int M)
{
    const int gid = blockIdx.x * 256 + threadIdx.x;
    const int node = gid >> 4;
    const int lane = gid & 15;
    if (node >= M) return;

    const bool active = (lane < 10);
    float a0 = 0.f, a1 = 0.f, a2 = 0.f, a3 = 0.f;

    if (active) {
        const int beg = row_off[node];
        const int end = row_off[node + 1];
        for (int j = beg; j < end; j++) {
            const int2 e = edges[j];
            const float w = __int_as_float(e.y);
            const uint2 raw = *(const uint2*)(sup + (size_t)e.x * 40 + lane * 4);
            const __half2* hp = (const __half2*)&raw;
            const float2 f0 = __half22float2(hp[0]);
            const float2 f1 = __half22float2(hp[1]);
            a0 += f0.x * w; a1 += f0.y * w;
            a2 += f1.x * w; a3 += f1.y * w;
        }
    }

    float m = -INFINITY;
    if (active) {
        const float* b = bias + lane * 4;
        a0 += b[0]; a1 += b[1]; a2 += b[2]; a3 += b[3];
        m = fmaxf(fmaxf(a0, a1), fmaxf(a2, a3));
    }
    #pragma unroll
    for (int off = 8; off > 0; off >>= 1)
        m = fmaxf(m, __shfl_xor_sync(0xFFFFFFFFu, m, off));
    float s = 0.f;
    if (active)
        s = expf(a0 - m) + expf(a1 - m) + expf(a2 - m) + expf(a3 - m);
    #pragma unroll
    for (int off = 8; off > 0; off >>= 1)
        s += __shfl_xor_sync(0xFFFFFFFFu, s, off);
    const float lse = m + logf(s);
    if (active) {
        float* o = out + (size_t)node * 40 + lane * 4;
        o[0] = a0 - lse; o[1] = a1 - lse; o[2] = a2 - lse; o[3] = a3 - lse;
    }
}

// ---------------------------------------------------------------------------
// Launch (single stream)
// ---------------------------------------------------------------------------
extern "C" void kernel_launch(void* const* d_in, const int* in_sizes, int n_in,
                              void* d_out, int out_size)
{
    const float* x   = (const float*)d_in[0];
    const int*   src = (const int*)d_in[1];
    const int*   tgt = (const int*)d_in[2];
    const float* mw  = (const float*)d_in[3];
    const float* W0  = (const float*)d_in[4];
    const float* b0  = (const float*)d_in[5];
    const float* W1  = (const float*)d_in[6];
    const float* b1  = (const float*)d_in[7];
    const float* W2  = (const float*)d_in[8];
    const float* b2  = (const float*)d_in[9];
    const float* W3  = (const float*)d_in[10];
    const float* b3  = (const float*)d_in[11];
    float* out = (float*)d_out;

    const int M = NN;
    const int E = in_sizes[1];

    __half *sup16, *h16;
    int *hcnt, *rowp, *rank, *blksum;
    int2 *edges;
    cudaGetSymbolAddress((void**)&sup16, g_sup16);
    cudaGetSymbolAddress((void**)&h16, g_h16);
    cudaGetSymbolAddress((void**)&hcnt, g_hcnt);
    cudaGetSymbolAddress((void**)&rowp, g_row);
    cudaGetSymbolAddress((void**)&rank, g_rank);
    cudaGetSymbolAddress((void**)&blksum, g_blksum);
    cudaGetSymbolAddress((void**)&edges, g_edge);

    const int nscan = M + 1;
    const int scan_blocks = (nscan + 1023) / 1024;
    const int eblocks = (E + 255) / 256;
    const int gemm_blocks = (M + 127) / 128;
    const int agg16_blocks = (M * 8 + 255) / 256;
    const int agg40_blocks = (M * 16 + 255) / 256;

    // ---- CSR build (by target); hcnt enters zeroed and leaves zeroed ----
    hist_rank_kernel<<<eblocks, 256>>>(tgt, hcnt, rank, E);
    scan1_kernel<<<scan_blocks, 1024>>>(hcnt, rowp, nscan, blksum);
    scan23_kernel<<<scan_blocks, 1024>>>(rowp, hcnt, nscan, blksum, scan_blocks);
    fill2_kernel<<<eblocks, 256>>>(src, tgt, mw, rowp, rank, edges, E);

    // ---- Layer 0: h = relu(agg(x@W0) + b0)
    hgemm_kernel<128, 64, true><<<gemm_blocks, 256>>>(x, (const __half*)0, W0, sup16, M);
    csr_agg16_kernel<0><<<agg16_blocks, 256>>>(sup16, rowp, edges, b0, h16, M);

    // ---- Layer 1: h = relu(agg(h@W1) + b1) + h
    hgemm_kernel<64, 64, false><<<gemm_blocks, 256>>>((const float*)0, h16, W1, sup16, M);
    csr_agg16_kernel<1><<<agg16_blocks, 256>>>(sup16, rowp, edges, b1, h16, M);

    // ---- Layer 2: h = relu(agg(h@W2) + b2) + h
    hgemm_kernel<64, 64, false><<<gemm_blocks, 256>>>((const float*)0, h16, W2, sup16, M);
    csr_agg16_kernel<1><<<agg16_blocks, 256>>>(sup16, rowp, edges, b2, h16, M);

    // ---- Layer 3: out = log_softmax(agg(h@W3) + b3)
    hgemm_kernel<64, 40, false><<<gemm_blocks, 256>>>((const float*)0, h16, W3, sup16, M);
    csr_agg40_final_kernel<<<agg40_blocks, 256>>>(sup16, rowp, edges, b3, out, M);
}

// round 14
// speedup vs baseline: 1.0466x; 1.0127x over previous
#include <cuda_runtime.h>
#include <cuda_fp16.h>
#include <cstdint>
#include <math.h>

#define NN 100000
#define EE 1600000

// Scratch (device globals — no allocations allowed; zero-initialized at load)
__device__ __align__(256) __half g_sup16[NN * 64];   // fp16 support (all layers)
__device__ __align__(256) __half g_h16[NN * 64];     // fp16 hidden state
__device__ __align__(256) int    g_hcnt[NN + 1];     // histogram (left zeroed each call)
__device__ __align__(256) int    g_row[NN + 1];      // row offsets (scan output)
__device__ __align__(256) int    g_rank[EE];         // per-edge within-target rank
__device__ __align__(256) int2   g_edge[EE];         // CSR payload: (src, w bits)
__device__ __align__(256) int    g_blksum[256];      // scan partials

// ---------------------------------------------------------------------------
// CSR build: hist_rank (one atomic pass, emits ranks) -> scan (2 kernels,
// re-zeroes hcnt) -> fill2 (atomic-free, grid-stride ILP-4)
// ---------------------------------------------------------------------------
__global__ __launch_bounds__(256) void hist_rank_kernel(
    const int* __restrict__ tgt, int* __restrict__ hcnt,
    int* __restrict__ rank, int E)
{
    int e = blockIdx.x * 256 + threadIdx.x;
    if (e < E) rank[e] = atomicAdd(&hcnt[tgt[e] + 1], 1);
}

__global__ __launch_bounds__(1024) void scan1_kernel(
    const int* __restrict__ hcnt, int* __restrict__ row, int n,
    int* __restrict__ blksum)
{
    __shared__ int wsum[32];
    const int tid = threadIdx.x;
    const int lane = tid & 31;
    const int warp = tid >> 5;
    const int i = blockIdx.x * 1024 + tid;
    int v = (i < n) ? hcnt[i] : 0;
    #pragma unroll
    for (int off = 1; off < 32; off <<= 1) {
        int t = __shfl_up_sync(0xFFFFFFFFu, v, off);
        if (lane >= off) v += t;
    }
    if (lane == 31) wsum[warp] = v;
    __syncthreads();
    if (warp == 0) {
        int s = wsum[lane];
        #pragma unroll
        for (int off = 1; off < 32; off <<= 1) {
            int t = __shfl_up_sync(0xFFFFFFFFu, s, off);
            if (lane >= off) s += t;
        }
        wsum[lane] = s;
    }
    __syncthreads();
    if (warp > 0) v += wsum[warp - 1];
    if (i < n) row[i] = v;
    if (tid == 1023) blksum[blockIdx.x] = v;
}

// Adds block prefixes (each block re-scans blksum itself) and zeroes hcnt.
__global__ __launch_bounds__(1024) void scan23_kernel(
    int* __restrict__ row, int* __restrict__ hcnt, int n,
    const int* __restrict__ blksum, int nb)
{
    __shared__ int pref[128];
    const int tid = threadIdx.x;
    if (tid < 128) pref[tid] = (tid < nb) ? blksum[tid] : 0;
    __syncthreads();
    #pragma unroll
    for (int off = 1; off < 128; off <<= 1) {
        int t = 0;
        if (tid < 128 && tid >= off) t = pref[tid - off];
        __syncthreads();
        if (tid < 128) pref[tid] += t;
        __syncthreads();
    }
    const int add = (blockIdx.x > 0) ? pref[blockIdx.x - 1] : 0;
    const int i = blockIdx.x * 1024 + tid;
    if (i >= n) return;
    row[i] += add;
    hcnt[i] = 0;   // restore invariant for next graph replay
}

// Atomic-free fill, grid-stride ILP-4: 4 independent gather->store chains.
__global__ __launch_bounds__(256) void fill2_kernel(
    const int* __restrict__ src, const int* __restrict__ tgt,
    const float* __restrict__ w, const int* __restrict__ row,
    const int* __restrict__ rank, int2* __restrict__ edges, int E, int stride)
{
    const int gid = blockIdx.x * 256 + threadIdx.x;
    int t[4], r[4], s[4];
    float ww[4];
    #pragma unroll
    for (int k = 0; k < 4; k++) {
        const int e = gid + k * stride;
        if (e < E) {
            t[k] = tgt[e];
            r[k] = rank[e];
            s[k] = src[e];
            ww[k] = w[e];
        } else t[k] = -1;
    }
    int pos[4];
    #pragma unroll
    for (int k = 0; k < 4; k++)
        if (t[k] >= 0) pos[k] = row[t[k]] + r[k];
    #pragma unroll
    for (int k = 0; k < 4; k++)
        if (t[k] >= 0)
            edges[pos[k]] = make_int2(s[k], __float_as_int(ww[k]));
}

// ---------------------------------------------------------------------------
// HMMA GEMM: C16[M,OUTC] = A[M,K] @ W[K,OUTC]  (fp16 in, fp32 accum, fp16 out)
// Tile: BM=128, BN=64, BK=64. 256 threads = 8 warps (4m x 2n), warp = 32x32.
// K=128 (A_FP32) path: software-pipelined — next A tile LDGs issued before
// current tile's MMAs.
// ---------------------------------------------------------------------------
#define SMEM_STRIDE 72   // halves per row (144 B) -> conflict-free LDSM

__device__ __forceinline__ unsigned smem_u32(const void* p) {
    return (unsigned)__cvta_generic_to_shared(p);
}

__device__ __forceinline__ void ldsm_x4(unsigned& r0, unsigned& r1,
                                        unsigned& r2, unsigned& r3, unsigned a) {
    asm volatile("ldmatrix.sync.aligned.m8n8.x4.shared.b16 {%0,%1,%2,%3}, [%4];"
                 : "=r"(r0), "=r"(r1), "=r"(r2), "=r"(r3) : "r"(a));
}
__device__ __forceinline__ void ldsm_x4_t(unsigned& r0, unsigned& r1,
                                          unsigned& r2, unsigned& r3, unsigned a) {
    asm volatile("ldmatrix.sync.aligned.m8n8.x4.trans.shared.b16 {%0,%1,%2,%3}, [%4];"
                 : "=r"(r0), "=r"(r1), "=r"(r2), "=r"(r3) : "r"(a));
}
__device__ __forceinline__ void mma16816(float c[4], const unsigned a[4],
                                         unsigned b0, unsigned b1) {
    asm volatile(
        "mma.sync.aligned.m16n8k16.row.col.f32.f16.f16.f32 "
        "{%0,%1,%2,%3}, {%4,%5,%6,%7}, {%8,%9}, {%0,%1,%2,%3};"
        : "+f"(c[0]), "+f"(c[1]), "+f"(c[2]), "+f"(c[3])
        : "r"(a[0]), "r"(a[1]), "r"(a[2]), "r"(a[3]), "r"(b0), "r"(b1));
}

template <int K, int OUTC, bool A_FP32>
__global__ __launch_bounds__(256) void hgemm_kernel(
    const float* __restrict__ A32, const __half* __restrict__ A16,
    const float* __restrict__ W, __half* __restrict__ C16, int M)
{
    __shared__ __half a_s[128 * SMEM_STRIDE];
    __shared__ __half b_s[64 * SMEM_STRIDE];

    const int tid = threadIdx.x;
    const int lane = tid & 31;
    const int wid = tid >> 5;
    const int wm = (wid >> 1) * 32;
    const int wn = (wid & 1) * 32;
    const int row0 = blockIdx.x * 128;

    float c[2][4][4] = {};

    // ---- Prologue: load tiles for k0 = 0 ----
    // B tile
    #pragma unroll
    for (int p = 0; p < 4; p++) {
        const int idx = tid + p * 256;
        const int row = idx >> 4;
        const int ch = idx & 15;
        uint2 st = make_uint2(0u, 0u);
        if (OUTC == 64 || ch * 4 < OUTC) {
            const float4 v = *(const float4*)&W[(size_t)row * OUTC + ch * 4];
            __half2 h0 = __floats2half2_rn(v.x, v.y);
            __half2 h1 = __floats2half2_rn(v.z, v.w);
            st.x = *(const unsigned*)&h0;
            st.y = *(const unsigned*)&h1;
        }
        *(uint2*)&b_s[row * SMEM_STRIDE + ch * 4] = st;
    }
    // A tile (k0 = 0)
    if (A_FP32) {
        #pragma unroll
        for (int q = 0; q < 8; q++) {
            const int idx = tid + q * 256;
            const int row = idx >> 4;
            const int ch = idx & 15;
            const int grow = row0 + row;
            float4 v = make_float4(0.f, 0.f, 0.f, 0.f);
            if (grow < M) v = *(const float4*)&A32[(size_t)grow * K + ch * 4];
            __half2 h0 = __floats2half2_rn(v.x, v.y);
            __half2 h1 = __floats2half2_rn(v.z, v.w);
            uint2 st;
            st.x = *(const unsigned*)&h0;
            st.y = *(const unsigned*)&h1;
            *(uint2*)&a_s[row * SMEM_STRIDE + ch * 4] = st;
        }
    } else {
        #pragma unroll
        for (int p = 0; p < 4; p++) {
            const int idx = tid + p * 256;
            const int row = idx >> 3;
            const int ch = idx & 7;
            const int grow = row0 + row;
            uint4 v = make_uint4(0u, 0u, 0u, 0u);
            if (grow < M) v = *(const uint4*)&A16[(size_t)grow * K + ch * 8];
            *(uint4*)&a_s[row * SMEM_STRIDE + ch * 8] = v;
        }
    }
    __syncthreads();

    for (int k0 = 0; k0 < K; k0 += 64) {
        const bool have_next = (k0 + 64 < K);

        // ---- Prefetch next A tile into registers (overlap with MMAs) ----
        float4 preA[8];
        if (A_FP32 && have_next) {
            #pragma unroll
            for (int q = 0; q < 8; q++) {
                const int idx = tid + q * 256;
                const int row = idx >> 4;
                const int ch = idx & 15;
                const int grow = row0 + row;
                preA[q] = make_float4(0.f, 0.f, 0.f, 0.f);
                if (grow < M)
                    preA[q] = *(const float4*)&A32[(size_t)grow * K + k0 + 64 + ch * 4];
            }
        }

        // ---- MMAs on current smem tiles ----
        #pragma unroll
        for (int ks = 0; ks < 4; ks++) {
            const int k = ks * 16;
            unsigned a[2][4];
            #pragma unroll
            for (int mt = 0; mt < 2; mt++) {
                const int r = wm + mt * 16 + (lane & 15);
                const int cc = k + (lane >> 4) * 8;
                ldsm_x4(a[mt][0], a[mt][1], a[mt][2], a[mt][3],
                        smem_u32(&a_s[r * SMEM_STRIDE + cc]));
            }
            unsigned b[2][4];
            #pragma unroll
            for (int nt2 = 0; nt2 < 2; nt2++) {
                const int kr = k + (lane & 15);
                const int nc = wn + nt2 * 16 + (lane >> 4) * 8;
                ldsm_x4_t(b[nt2][0], b[nt2][1], b[nt2][2], b[nt2][3],
                          smem_u32(&b_s[kr * SMEM_STRIDE + nc]));
            }
            #pragma unroll
            for (int mt = 0; mt < 2; mt++)
                #pragma unroll
                for (int nt = 0; nt < 4; nt++)
                    mma16816(c[mt][nt], a[mt],
                             b[nt >> 1][(nt & 1) * 2], b[nt >> 1][(nt & 1) * 2 + 1]);
        }

        // ---- Commit next tiles ----
        if (have_next) {
            __syncthreads();   // all reads of current tiles done
            if (A_FP32) {
                #pragma unroll
                for (int q = 0; q < 8; q++) {
                    const int idx = tid + q * 256;
                    const int row = idx >> 4;
                    const int ch = idx & 15;
                    __half2 h0 = __floats2half2_rn(preA[q].x, preA[q].y);
                    __half2 h1 = __floats2half2_rn(preA[q].z, preA[q].w);
                    uint2 st;
                    st.x = *(const unsigned*)&h0;
                    st.y = *(const unsigned*)&h1;
                    *(uint2*)&a_s[row * SMEM_STRIDE + ch * 4] = st;
                }
            } else {
                #pragma unroll
                for (int p = 0; p < 4; p++) {
                    const int idx = tid + p * 256;
                    const int row = idx >> 3;
                    const int ch = idx & 7;
                    const int grow = row0 + row;
                    uint4 v = make_uint4(0u, 0u, 0u, 0u);
                    if (grow < M)
                        v = *(const uint4*)&A16[(size_t)grow * K + k0 + 64 + ch * 8];
                    *(uint4*)&a_s[row * SMEM_STRIDE + ch * 8] = v;
                }
            }
            // B tile for next iteration (L2-resident W — short latency)
            #pragma unroll
            for (int p = 0; p < 4; p++) {
                const int idx = tid + p * 256;
                const int row = idx >> 4;
                const int ch = idx & 15;
                uint2 st = make_uint2(0u, 0u);
                if (OUTC == 64 || ch * 4 < OUTC) {
                    const float4 v =
                        *(const float4*)&W[(size_t)(k0 + 64 + row) * OUTC + ch * 4];
                    __half2 h0 = __floats2half2_rn(v.x, v.y);
                    __half2 h1 = __floats2half2_rn(v.z, v.w);
                    st.x = *(const unsigned*)&h0;
                    st.y = *(const unsigned*)&h1;
                }
                *(uint2*)&b_s[row * SMEM_STRIDE + ch * 4] = st;
            }
            __syncthreads();
        }
    }

    #pragma unroll
    for (int mt = 0; mt < 2; mt++) {
        #pragma unroll
        for (int nt = 0; nt < 4; nt++) {
            const int col = wn + nt * 8 + (lane & 3) * 2;
            if (OUTC == 64 || col < OUTC) {
                const int r0 = row0 + wm + mt * 16 + (lane >> 2);
                if (r0 < M) {
                    __half2 v = __floats2half2_rn(c[mt][nt][0], c[mt][nt][1]);
                    *(__half2*)&C16[(size_t)r0 * OUTC + col] = v;
                }
                const int r1 = r0 + 8;
                if (r1 < M) {
                    __half2 v = __floats2half2_rn(c[mt][nt][2], c[mt][nt][3]);
                    *(__half2*)&C16[(size_t)r1 * OUTC + col] = v;
                }
            }
        }
    }
}

// ---------------------------------------------------------------------------
// fp16 CSR aggregate (COLS=64) + fused epilogue. 8 threads/node, 8 halves each.
// MODE 0: h16 = relu(agg+b);  MODE 1: h16 = relu(agg+b) + h16
// ---------------------------------------------------------------------------
__device__ __forceinline__ void acc_edge16(
    float acc[8], const __half* __restrict__ sup, int s, float w, int lane)
{
    const uint4 raw = *(const uint4*)(sup + (size_t)s * 64 + lane * 8);
    const __half2* hp = (const __half2*)&raw;
    #pragma unroll
    for (int p = 0; p < 4; p++) {
        const float2 f = __half22float2(hp[p]);
        acc[p * 2 + 0] += f.x * w;
        acc[p * 2 + 1] += f.y * w;
    }
}

template <int MODE>
__global__ __launch_bounds__(256) void csr_agg16_kernel(
    const __half* __restrict__ sup, const int* __restrict__ row_off,
    const int2* __restrict__ edges, const float* __restrict__ bias,
    __half* __restrict__ h16, int M)
{
    const int gid = blockIdx.x * 256 + threadIdx.x;
    const int node = gid >> 3;
    const int lane = gid & 7;
    if (node >= M) return;

    const int beg = row_off[node];
    const int end = row_off[node + 1];

    float acc[8] = {};
    int j = beg;
    for (; j + 1 < end; j += 2) {
        const int2 e0 = edges[j];
        const int2 e1 = edges[j + 1];
        acc_edge16(acc, sup, e0.x, __int_as_float(e0.y), lane);
        acc_edge16(acc, sup, e1.x, __int_as_float(e1.y), lane);
    }
    if (j < end) {
        const int2 e0 = edges[j];
        acc_edge16(acc, sup, e0.x, __int_as_float(e0.y), lane);
    }

    const float4 b0 = ((const float4*)bias)[lane * 2];
    const float4 b1 = ((const float4*)bias)[lane * 2 + 1];
    const float bb[8] = {b0.x, b0.y, b0.z, b0.w, b1.x, b1.y, b1.z, b1.w};
    float res[8];
    #pragma unroll
    for (int p = 0; p < 8; p++) res[p] = fmaxf(acc[p] + bb[p], 0.f);

    __half* hp = h16 + (size_t)node * 64 + lane * 8;
    if (MODE == 1) {
        const uint4 rraw = *(const uint4*)hp;
        const __half2* rh = (const __half2*)&rraw;
        #pragma unroll
        for (int p = 0; p < 4; p++) {
            const float2 f = __half22float2(rh[p]);
            res[p * 2 + 0] += f.x;
            res[p * 2 + 1] += f.y;
        }
    }

    uint4 st;
    __half2 q0 = __floats2half2_rn(res[0], res[1]);
    __half2 q1 = __floats2half2_rn(res[2], res[3]);
    __half2 q2 = __floats2half2_rn(res[4], res[5]);
    __half2 q3 = __floats2half2_rn(res[6], res[7]);
    st.x = *(const unsigned*)&q0; st.y = *(const unsigned*)&q1;
    st.z = *(const unsigned*)&q2; st.w = *(const unsigned*)&q3;
    *(uint4*)hp = st;
}

// ---------------------------------------------------------------------------
// fp16 CSR aggregate, COLS=40, fused log_softmax (final layer).
// 16 threads/node; lanes 0-9 hold 4 halves (uint2) each.
// ---------------------------------------------------------------------------
__global__ __launch_bounds__(256) void csr_agg40_final_kernel(
    const __half* __restrict__ sup, const int* __restrict__ row_off,
    const int2* __restrict__ edges, const float* __restrict__ bias,
    float* __restrict__ out, int M)
{
    const int gid = blockIdx.x * 256 + threadIdx.x;
    const int node = gid >> 4;
    const int lane = gid & 15;
    if (node >= M) return;

    const bool active = (lane < 10);
    float a0 = 0.f, a1 = 0.f, a2 = 0.f, a3 = 0.f;

    if (active) {
        const int beg = row_off[node];
        const int end = row_off[node + 1];
        for (int j = beg; j < end; j++) {
            const int2 e = edges[j];
            const float w = __int_as_float(e.y);
            const uint2 raw = *(const uint2*)(sup + (size_t)e.x * 40 + lane * 4);
            const __half2* hp = (const __half2*)&raw;
            const float2 f0 = __half22float2(hp[0]);
            const float2 f1 = __half22float2(hp[1]);
            a0 += f0.x * w; a1 += f0.y * w;
            a2 += f1.x * w; a3 += f1.y * w;
        }
    }

    float m = -INFINITY;
    if (active) {
        const float* b = bias + lane * 4;
        a0 += b[0]; a1 += b[1]; a2 += b[2]; a3 += b[3];
        m = fmaxf(fmaxf(a0, a1), fmaxf(a2, a3));
    }
    #pragma unroll
    for (int off = 8; off > 0; off >>= 1)
        m = fmaxf(m, __shfl_xor_sync(0xFFFFFFFFu, m, off));
    float s = 0.f;
    if (active)
        s = expf(a0 - m) + expf(a1 - m) + expf(a2 - m) + expf(a3 - m);
    #pragma unroll
    for (int off = 8; off > 0; off >>= 1)
        s += __shfl_xor_sync(0xFFFFFFFFu, s, off);
    const float lse = m + logf(s);
    if (active) {
        float* o = out + (size_t)node * 40 + lane * 4;
        o[0] = a0 - lse; o[1] = a1 - lse; o[2] = a2 - lse; o[3] = a3 - lse;
    }
}

// ---------------------------------------------------------------------------
// Launch (single stream)
// ---------------------------------------------------------------------------
extern "C" void kernel_launch(void* const* d_in, const int* in_sizes, int n_in,
                              void* d_out, int out_size)
{
    const float* x   = (const float*)d_in[0];
    const int*   src = (const int*)d_in[1];
    const int*   tgt = (const int*)d_in[2];
    const float* mw  = (const float*)d_in[3];
    const float* W0  = (const float*)d_in[4];
    const float* b0  = (const float*)d_in[5];
    const float* W1  = (const float*)d_in[6];
    const float* b1  = (const float*)d_in[7];
    const float* W2  = (const float*)d_in[8];
    const float* b2  = (const float*)d_in[9];
    const float* W3  = (const float*)d_in[10];
    const float* b3  = (const float*)d_in[11];
    float* out = (float*)d_out;

    const int M = NN;
    const int E = in_sizes[1];

    __half *sup16, *h16;
    int *hcnt, *rowp, *rank, *blksum;
    int2 *edges;
    cudaGetSymbolAddress((void**)&sup16, g_sup16);
    cudaGetSymbolAddress((void**)&h16, g_h16);
    cudaGetSymbolAddress((void**)&hcnt, g_hcnt);
    cudaGetSymbolAddress((void**)&rowp, g_row);
    cudaGetSymbolAddress((void**)&rank, g_rank);
    cudaGetSymbolAddress((void**)&blksum, g_blksum);
    cudaGetSymbolAddress((void**)&edges, g_edge);

    const int nscan = M + 1;
    const int scan_blocks = (nscan + 1023) / 1024;
    const int eblocks = (E + 255) / 256;
    const int fill_blocks = (E + 1023) / 1024;        // ILP-4 grid-stride
    const int fill_stride = fill_blocks * 256;
    const int gemm_blocks = (M + 127) / 128;
    const int agg16_blocks = (M * 8 + 255) / 256;
    const int agg40_blocks = (M * 16 + 255) / 256;

    // ---- CSR build (by target); hcnt enters zeroed and leaves zeroed ----
    hist_rank_kernel<<<eblocks, 256>>>(tgt, hcnt, rank, E);
    scan1_kernel<<<scan_blocks, 1024>>>(hcnt, rowp, nscan, blksum);
    scan23_kernel<<<scan_blocks, 1024>>>(rowp, hcnt, nscan, blksum, scan_blocks);
    fill2_kernel<<<fill_blocks, 256>>>(src, tgt, mw, rowp, rank, edges, E, fill_stride);

    // ---- Layer 0: h = relu(agg(x@W0) + b0)
    hgemm_kernel<128, 64, true><<<gemm_blocks, 256>>>(x, (const __half*)0, W0, sup16, M);
    csr_agg16_kernel<0><<<agg16_blocks, 256>>>(sup16, rowp, edges, b0, h16, M);

    // ---- Layer 1: h = relu(agg(h@W1) + b1) + h
    hgemm_kernel<64, 64, false><<<gemm_blocks, 256>>>((const float*)0, h16, W1, sup16, M);
    csr_agg16_kernel<1><<<agg16_blocks, 256>>>(sup16, rowp, edges, b1, h16, M);

    // ---- Layer 2: h = relu(agg(h@W2) + b2) + h
    hgemm_kernel<64, 64, false><<<gemm_blocks, 256>>>((const float*)0, h16, W2, sup16, M);
    csr_agg16_kernel<1><<<agg16_blocks, 256>>>(sup16, rowp, edges, b2, h16, M);

    // ---- Layer 3: out = log_softmax(agg(h@W3) + b3)
    hgemm_kernel<64, 40, false><<<gemm_blocks, 256>>>((const float*)0, h16, W3, sup16, M);
    csr_agg40_final_kernel<<<agg40_blocks, 256>>>(sup16, rowp, edges, b3, out, M);
}

// round 15
// speedup vs baseline: 1.0557x; 1.0088x over previous
#include <cuda_runtime.h>
#include <cuda_fp16.h>
#include <cstdint>
#include <math.h>

#define NN 100000
#define EE 1600000

// Scratch (device globals — no allocations allowed; zero-initialized at load)
__device__ __align__(256) __half g_sup16[NN * 64];   // fp16 support (stride 64, all layers)
__device__ __align__(256) __half g_h16[NN * 64];     // fp16 hidden state
__device__ __align__(256) int    g_hcnt[NN + 1];     // histogram (left zeroed each call)
__device__ __align__(256) int    g_row[NN + 1];      // row offsets (scan output)
__device__ __align__(256) int    g_rank[EE];         // per-edge within-target rank
__device__ __align__(256) int2   g_edge[EE];         // CSR payload: (src, w bits)
__device__ __align__(256) int    g_blksum[256];      // scan partials

// ---------------------------------------------------------------------------
// CSR build: hist_rank -> scan (2 kernels, re-zeroes hcnt) -> fill2
// ---------------------------------------------------------------------------
__global__ __launch_bounds__(256) void hist_rank_kernel(
    const int* __restrict__ tgt, int* __restrict__ hcnt,
    int* __restrict__ rank, int E)
{
    int e = blockIdx.x * 256 + threadIdx.x;
    if (e < E) rank[e] = atomicAdd(&hcnt[tgt[e] + 1], 1);
}

__global__ __launch_bounds__(1024) void scan1_kernel(
    const int* __restrict__ hcnt, int* __restrict__ row, int n,
    int* __restrict__ blksum)
{
    __shared__ int wsum[32];
    const int tid = threadIdx.x;
    const int lane = tid & 31;
    const int warp = tid >> 5;
    const int i = blockIdx.x * 1024 + tid;
    int v = (i < n) ? hcnt[i] : 0;
    #pragma unroll
    for (int off = 1; off < 32; off <<= 1) {
        int t = __shfl_up_sync(0xFFFFFFFFu, v, off);
        if (lane >= off) v += t;
    }
    if (lane == 31) wsum[warp] = v;
    __syncthreads();
    if (warp == 0) {
        int s = wsum[lane];
        #pragma unroll
        for (int off = 1; off < 32; off <<= 1) {
            int t = __shfl_up_sync(0xFFFFFFFFu, s, off);
            if (lane >= off) s += t;
        }
        wsum[lane] = s;
    }
    __syncthreads();
    if (warp > 0) v += wsum[warp - 1];
    if (i < n) row[i] = v;
    if (tid == 1023) blksum[blockIdx.x] = v;
}

__global__ __launch_bounds__(1024) void scan23_kernel(
    int* __restrict__ row, int* __restrict__ hcnt, int n,
    const int* __restrict__ blksum, int nb)
{
    __shared__ int pref[128];
    const int tid = threadIdx.x;
    if (tid < 128) pref[tid] = (tid < nb) ? blksum[tid] : 0;
    __syncthreads();
    #pragma unroll
    for (int off = 1; off < 128; off <<= 1) {
        int t = 0;
        if (tid < 128 && tid >= off) t = pref[tid - off];
        __syncthreads();
        if (tid < 128) pref[tid] += t;
        __syncthreads();
    }
    const int add = (blockIdx.x > 0) ? pref[blockIdx.x - 1] : 0;
    const int i = blockIdx.x * 1024 + tid;
    if (i >= n) return;
    row[i] += add;
    hcnt[i] = 0;   // restore invariant for next graph replay
}

// Atomic-free fill (1 edge/thread — bandwidth-bound; ILP was neutral).
__global__ __launch_bounds__(256) void fill2_kernel(
    const int* __restrict__ src, const int* __restrict__ tgt,
    const float* __restrict__ w, const int* __restrict__ row,
    const int* __restrict__ rank, int2* __restrict__ edges, int E)
{
    int e = blockIdx.x * 256 + threadIdx.x;
    if (e >= E) return;
    const int pos = row[tgt[e]] + rank[e];
    edges[pos] = make_int2(src[e], __float_as_int(w[e]));
}

// ---------------------------------------------------------------------------
// HMMA GEMM: C16[M, stride64] = A[M,K] @ W[K,OUTC]  (fp32 accum, fp16 out)
// Output row stride fixed at 64 (layer-3's 40 cols are padded -> aligned rows).
// K=128 (A_FP32) path: software-pipelined.
// ---------------------------------------------------------------------------
#define SMEM_STRIDE 72   // halves per row (144 B) -> conflict-free LDSM

__device__ __forceinline__ unsigned smem_u32(const void* p) {
    return (unsigned)__cvta_generic_to_shared(p);
}

__device__ __forceinline__ void ldsm_x4(unsigned& r0, unsigned& r1,
                                        unsigned& r2, unsigned& r3, unsigned a) {
    asm volatile("ldmatrix.sync.aligned.m8n8.x4.shared.b16 {%0,%1,%2,%3}, [%4];"
                 : "=r"(r0), "=r"(r1), "=r"(r2), "=r"(r3) : "r"(a));
}
__device__ __forceinline__ void ldsm_x4_t(unsigned& r0, unsigned& r1,
                                          unsigned& r2, unsigned& r3, unsigned a) {
    asm volatile("ldmatrix.sync.aligned.m8n8.x4.trans.shared.b16 {%0,%1,%2,%3}, [%4];"
                 : "=r"(r0), "=r"(r1), "=r"(r2), "=r"(r3) : "r"(a));
}
__device__ __forceinline__ void mma16816(float c[4], const unsigned a[4],
                                         unsigned b0, unsigned b1) {
    asm volatile(
        "mma.sync.aligned.m16n8k16.row.col.f32.f16.f16.f32 "
        "{%0,%1,%2,%3}, {%4,%5,%6,%7}, {%8,%9}, {%0,%1,%2,%3};"
        : "+f"(c[0]), "+f"(c[1]), "+f"(c[2]), "+f"(c[3])
        : "r"(a[0]), "r"(a[1]), "r"(a[2]), "r"(a[3]), "r"(b0), "r"(b1));
}

template <int K, int OUTC, bool A_FP32>
__global__ __launch_bounds__(256) void hgemm_kernel(
    const float* __restrict__ A32, const __half* __restrict__ A16,
    const float* __restrict__ W, __half* __restrict__ C16, int M)
{
    __shared__ __half a_s[128 * SMEM_STRIDE];
    __shared__ __half b_s[64 * SMEM_STRIDE];

    const int tid = threadIdx.x;
    const int lane = tid & 31;
    const int wid = tid >> 5;
    const int wm = (wid >> 1) * 32;
    const int wn = (wid & 1) * 32;
    const int row0 = blockIdx.x * 128;

    float c[2][4][4] = {};

    // ---- Prologue: tiles for k0 = 0 ----
    #pragma unroll
    for (int p = 0; p < 4; p++) {
        const int idx = tid + p * 256;
        const int row = idx >> 4;
        const int ch = idx & 15;
        uint2 st = make_uint2(0u, 0u);
        if (OUTC == 64 || ch * 4 < OUTC) {
            const float4 v = *(const float4*)&W[(size_t)row * OUTC + ch * 4];
            __half2 h0 = __floats2half2_rn(v.x, v.y);
            __half2 h1 = __floats2half2_rn(v.z, v.w);
            st.x = *(const unsigned*)&h0;
            st.y = *(const unsigned*)&h1;
        }
        *(uint2*)&b_s[row * SMEM_STRIDE + ch * 4] = st;
    }
    if (A_FP32) {
        #pragma unroll
        for (int q = 0; q < 8; q++) {
            const int idx = tid + q * 256;
            const int row = idx >> 4;
            const int ch = idx & 15;
            const int grow = row0 + row;
            float4 v = make_float4(0.f, 0.f, 0.f, 0.f);
            if (grow < M) v = *(const float4*)&A32[(size_t)grow * K + ch * 4];
            __half2 h0 = __floats2half2_rn(v.x, v.y);
            __half2 h1 = __floats2half2_rn(v.z, v.w);
            uint2 st;
            st.x = *(const unsigned*)&h0;
            st.y = *(const unsigned*)&h1;
            *(uint2*)&a_s[row * SMEM_STRIDE + ch * 4] = st;
        }
    } else {
        #pragma unroll
        for (int p = 0; p < 4; p++) {
            const int idx = tid + p * 256;
            const int row = idx >> 3;
            const int ch = idx & 7;
            const int grow = row0 + row;
            uint4 v = make_uint4(0u, 0u, 0u, 0u);
            if (grow < M) v = *(const uint4*)&A16[(size_t)grow * K + ch * 8];
            *(uint4*)&a_s[row * SMEM_STRIDE + ch * 8] = v;
        }
    }
    __syncthreads();

    for (int k0 = 0; k0 < K; k0 += 64) {
        const bool have_next = (k0 + 64 < K);

        float4 preA[8];
        if (A_FP32 && have_next) {
            #pragma unroll
            for (int q = 0; q < 8; q++) {
                const int idx = tid + q * 256;
                const int row = idx >> 4;
                const int ch = idx & 15;
                const int grow = row0 + row;
                preA[q] = make_float4(0.f, 0.f, 0.f, 0.f);
                if (grow < M)
                    preA[q] = *(const float4*)&A32[(size_t)grow * K + k0 + 64 + ch * 4];
            }
        }

        #pragma unroll
        for (int ks = 0; ks < 4; ks++) {
            const int k = ks * 16;
            unsigned a[2][4];
            #pragma unroll
            for (int mt = 0; mt < 2; mt++) {
                const int r = wm + mt * 16 + (lane & 15);
                const int cc = k + (lane >> 4) * 8;
                ldsm_x4(a[mt][0], a[mt][1], a[mt][2], a[mt][3],
                        smem_u32(&a_s[r * SMEM_STRIDE + cc]));
            }
            unsigned b[2][4];
            #pragma unroll
            for (int nt2 = 0; nt2 < 2; nt2++) {
                const int kr = k + (lane & 15);
                const int nc = wn + nt2 * 16 + (lane >> 4) * 8;
                ldsm_x4_t(b[nt2][0], b[nt2][1], b[nt2][2], b[nt2][3],
                          smem_u32(&b_s[kr * SMEM_STRIDE + nc]));
            }
            #pragma unroll
            for (int mt = 0; mt < 2; mt++)
                #pragma unroll
                for (int nt = 0; nt < 4; nt++)
                    mma16816(c[mt][nt], a[mt],
                             b[nt >> 1][(nt & 1) * 2], b[nt >> 1][(nt & 1) * 2 + 1]);
        }

        if (have_next) {
            __syncthreads();
            if (A_FP32) {
                #pragma unroll
                for (int q = 0; q < 8; q++) {
                    const int idx = tid + q * 256;
                    const int row = idx >> 4;
                    const int ch = idx & 15;
                    __half2 h0 = __floats2half2_rn(preA[q].x, preA[q].y);
                    __half2 h1 = __floats2half2_rn(preA[q].z, preA[q].w);
                    uint2 st;
                    st.x = *(const unsigned*)&h0;
                    st.y = *(const unsigned*)&h1;
                    *(uint2*)&a_s[row * SMEM_STRIDE + ch * 4] = st;
                }
            } else {
                #pragma unroll
                for (int p = 0; p < 4; p++) {
                    const int idx = tid + p * 256;
                    const int row = idx >> 3;
                    const int ch = idx & 7;
                    const int grow = row0 + row;
                    uint4 v = make_uint4(0u, 0u, 0u, 0u);
                    if (grow < M)
                        v = *(const uint4*)&A16[(size_t)grow * K + k0 + 64 + ch * 8];
                    *(uint4*)&a_s[row * SMEM_STRIDE + ch * 8] = v;
                }
            }
            #pragma unroll
            for (int p = 0; p < 4; p++) {
                const int idx = tid + p * 256;
                const int row = idx >> 4;
                const int ch = idx & 15;
                uint2 st = make_uint2(0u, 0u);
                if (OUTC == 64 || ch * 4 < OUTC) {
                    const float4 v =
                        *(const float4*)&W[(size_t)(k0 + 64 + row) * OUTC + ch * 4];
                    __half2 h0 = __floats2half2_rn(v.x, v.y);
                    __half2 h1 = __floats2half2_rn(v.z, v.w);
                    st.x = *(const unsigned*)&h0;
                    st.y = *(const unsigned*)&h1;
                }
                *(uint2*)&b_s[row * SMEM_STRIDE + ch * 4] = st;
            }
            __syncthreads();
        }
    }

    // Store at fixed row stride 64 (pads layer-3's 40 cols)
    #pragma unroll
    for (int mt = 0; mt < 2; mt++) {
        #pragma unroll
        for (int nt = 0; nt < 4; nt++) {
            const int col = wn + nt * 8 + (lane & 3) * 2;
            if (OUTC == 64 || col < OUTC) {
                const int r0 = row0 + wm + mt * 16 + (lane >> 2);
                if (r0 < M) {
                    __half2 v = __floats2half2_rn(c[mt][nt][0], c[mt][nt][1]);
                    *(__half2*)&C16[(size_t)r0 * 64 + col] = v;
                }
                const int r1 = r0 + 8;
                if (r1 < M) {
                    __half2 v = __floats2half2_rn(c[mt][nt][2], c[mt][nt][3]);
                    *(__half2*)&C16[(size_t)r1 * 64 + col] = v;
                }
            }
        }
    }
}

// ---------------------------------------------------------------------------
// fp16 CSR aggregate (COLS=64) + fused epilogue. 8 threads/node, 8 halves each.
// MODE 0: h16 = relu(agg+b);  MODE 1: h16 = relu(agg+b) + h16
// ---------------------------------------------------------------------------
__device__ __forceinline__ void acc_edge16(
    float acc[8], const __half* __restrict__ sup, int s, float w, int lane)
{
    const uint4 raw = *(const uint4*)(sup + (size_t)s * 64 + lane * 8);
    const __half2* hp = (const __half2*)&raw;
    #pragma unroll
    for (int p = 0; p < 4; p++) {
        const float2 f = __half22float2(hp[p]);
        acc[p * 2 + 0] += f.x * w;
        acc[p * 2 + 1] += f.y * w;
    }
}

template <int MODE>
__global__ __launch_bounds__(256) void csr_agg16_kernel(
    const __half* __restrict__ sup, const int* __restrict__ row_off,
    const int2* __restrict__ edges, const float* __restrict__ bias,
    __half* __restrict__ h16, int M)
{
    const int gid = blockIdx.x * 256 + threadIdx.x;
    const int node = gid >> 3;
    const int lane = gid & 7;
    if (node >= M) return;

    const int beg = row_off[node];
    const int end = row_off[node + 1];

    float acc[8] = {};
    int j = beg;
    for (; j + 1 < end; j += 2) {
        const int2 e0 = edges[j];
        const int2 e1 = edges[j + 1];
        acc_edge16(acc, sup, e0.x, __int_as_float(e0.y), lane);
        acc_edge16(acc, sup, e1.x, __int_as_float(e1.y), lane);
    }
    if (j < end) {
        const int2 e0 = edges[j];
        acc_edge16(acc, sup, e0.x, __int_as_float(e0.y), lane);
    }

    const float4 b0 = ((const float4*)bias)[lane * 2];
    const float4 b1 = ((const float4*)bias)[lane * 2 + 1];
    const float bb[8] = {b0.x, b0.y, b0.z, b0.w, b1.x, b1.y, b1.z, b1.w};
    float res[8];
    #pragma unroll
    for (int p = 0; p < 8; p++) res[p] = fmaxf(acc[p] + bb[p], 0.f);

    __half* hp = h16 + (size_t)node * 64 + lane * 8;
    if (MODE == 1) {
        const uint4 rraw = *(const uint4*)hp;
        const __half2* rh = (const __half2*)&rraw;
        #pragma unroll
        for (int p = 0; p < 4; p++) {
            const float2 f = __half22float2(rh[p]);
            res[p * 2 + 0] += f.x;
            res[p * 2 + 1] += f.y;
        }
    }

    uint4 st;
    __half2 q0 = __floats2half2_rn(res[0], res[1]);
    __half2 q1 = __floats2half2_rn(res[2], res[3]);
    __half2 q2 = __floats2half2_rn(res[4], res[5]);
    __half2 q3 = __floats2half2_rn(res[6], res[7]);
    st.x = *(const unsigned*)&q0; st.y = *(const unsigned*)&q1;
    st.z = *(const unsigned*)&q2; st.w = *(const unsigned*)&q3;
    *(uint4*)hp = st;
}

// ---------------------------------------------------------------------------
// fp16 CSR aggregate, 40 valid cols at row stride 64 (aligned rows),
// fused log_softmax. 16 threads/node; lanes 0-9 hold 4 halves each.
// ---------------------------------------------------------------------------
__global__ __launch_bounds__(256) void csr_agg40_final_kernel(
    const __half* __restrict__ sup, const int* __restrict__ row_off,
    const int2* __restrict__ edges, const float* __restrict__ bias,
    float* __restrict__ out, int M)
{
    const int gid = blockIdx.x * 256 + threadIdx.x;
    const int node = gid >> 4;
    const int lane = gid & 15;
    if (node >= M) return;

    const bool active = (lane < 10);
    float a0 = 0.f, a1 = 0.f, a2 = 0.f, a3 = 0.f;

    if (active) {
        const int beg = row_off[node];
        const int end = row_off[node + 1];
        for (int j = beg; j < end; j++) {
            const int2 e = edges[j];
            const float w = __int_as_float(e.y);
            const uint2 raw = *(const uint2*)(sup + (size_t)e.x * 64 + lane * 4);
            const __half2* hp = (const __half2*)&raw;
            const float2 f0 = __half22float2(hp[0]);
            const float2 f1 = __half22float2(hp[1]);
            a0 += f0.x * w; a1 += f0.y * w;
            a2 += f1.x * w; a3 += f1.y * w;
        }
    }

    float m = -INFINITY;
    if (active) {
        const float* b = bias + lane * 4;
        a0 += b[0]; a1 += b[1]; a2 += b[2]; a3 += b[3];
        m = fmaxf(fmaxf(a0, a1), fmaxf(a2, a3));
    }
    #pragma unroll
    for (int off = 8; off > 0; off >>= 1)
        m = fmaxf(m, __shfl_xor_sync(0xFFFFFFFFu, m, off));
    float s = 0.f;
    if (active)
        s = expf(a0 - m) + expf(a1 - m) + expf(a2 - m) + expf(a3 - m);
    #pragma unroll
    for (int off = 8; off > 0; off >>= 1)
        s += __shfl_xor_sync(0xFFFFFFFFu, s, off);
    const float lse = m + logf(s);
    if (active) {
        float* o = out + (size_t)node * 40 + lane * 4;
        o[0] = a0 - lse; o[1] = a1 - lse; o[2] = a2 - lse; o[3] = a3 - lse;
    }
}

// ---------------------------------------------------------------------------
// Launch: fork-join — layer-0 GEMM on side stream, CSR build on main.
// ---------------------------------------------------------------------------
extern "C" void kernel_launch(void* const* d_in, const int* in_sizes, int n_in,
                              void* d_out, int out_size)
{
    const float* x   = (const float*)d_in[0];
    const int*   src = (const int*)d_in[1];
    const int*   tgt = (const int*)d_in[2];
    const float* mw  = (const float*)d_in[3];
    const float* W0  = (const float*)d_in[4];
    const float* b0  = (const float*)d_in[5];
    const float* W1  = (const float*)d_in[6];
    const float* b1  = (const float*)d_in[7];
    const float* W2  = (const float*)d_in[8];
    const float* b2  = (const float*)d_in[9];
    const float* W3  = (const float*)d_in[10];
    const float* b3  = (const float*)d_in[11];
    float* out = (float*)d_out;

    const int M = NN;
    const int E = in_sizes[1];

    __half *sup16, *h16;
    int *hcnt, *rowp, *rank, *blksum;
    int2 *edges;
    cudaGetSymbolAddress((void**)&sup16, g_sup16);
    cudaGetSymbolAddress((void**)&h16, g_h16);
    cudaGetSymbolAddress((void**)&hcnt, g_hcnt);
    cudaGetSymbolAddress((void**)&rowp, g_row);
    cudaGetSymbolAddress((void**)&rank, g_rank);
    cudaGetSymbolAddress((void**)&blksum, g_blksum);
    cudaGetSymbolAddress((void**)&edges, g_edge);

    static cudaStream_t s2 = nullptr;
    static cudaEvent_t ev_fork = nullptr, ev_join = nullptr;
    if (s2 == nullptr) {
        cudaStreamCreateWithFlags(&s2, cudaStreamNonBlocking);
        cudaEventCreateWithFlags(&ev_fork, cudaEventDisableTiming);
        cudaEventCreateWithFlags(&ev_join, cudaEventDisableTiming);
    }

    const int nscan = M + 1;
    const int scan_blocks = (nscan + 1023) / 1024;
    const int eblocks = (E + 255) / 256;
    const int gemm_blocks = (M + 127) / 128;
    const int agg16_blocks = (M * 8 + 255) / 256;
    const int agg40_blocks = (M * 16 + 255) / 256;

    // ---- Fork: layer-0 GEMM (x, W0 only) on side stream ----
    cudaEventRecord(ev_fork, 0);
    cudaStreamWaitEvent(s2, ev_fork, 0);
    hgemm_kernel<128, 64, true><<<gemm_blocks, 256, 0, s2>>>(
        x, (const __half*)0, W0, sup16, M);
    cudaEventRecord(ev_join, s2);

    // ---- CSR build on main stream; hcnt enters zeroed and leaves zeroed ----
    hist_rank_kernel<<<eblocks, 256>>>(tgt, hcnt, rank, E);
    scan1_kernel<<<scan_blocks, 1024>>>(hcnt, rowp, nscan, blksum);
    scan23_kernel<<<scan_blocks, 1024>>>(rowp, hcnt, nscan, blksum, scan_blocks);
    fill2_kernel<<<eblocks, 256>>>(src, tgt, mw, rowp, rank, edges, E);

    // ---- Join ----
    cudaStreamWaitEvent(0, ev_join, 0);

    // ---- Layer 0: h = relu(agg(x@W0) + b0)
    csr_agg16_kernel<0><<<agg16_blocks, 256>>>(sup16, rowp, edges, b0, h16, M);

    // ---- Layer 1: h = relu(agg(h@W1) + b1) + h
    hgemm_kernel<64, 64, false><<<gemm_blocks, 256>>>((const float*)0, h16, W1, sup16, M);
    csr_agg16_kernel<1><<<agg16_blocks, 256>>>(sup16, rowp, edges, b1, h16, M);

    // ---- Layer 2: h = relu(agg(h@W2) + b2) + h
    hgemm_kernel<64, 64, false><<<gemm_blocks, 256>>>((const float*)0, h16, W2, sup16, M);
    csr_agg16_kernel<1><<<agg16_blocks, 256>>>(sup16, rowp, edges, b2, h16, M);

    // ---- Layer 3: out = log_softmax(agg(h@W3) + b3)  (sup stride 64)
    hgemm_kernel<64, 40, false><<<gemm_blocks, 256>>>((const float*)0, h16, W3, sup16, M);
    csr_agg40_final_kernel<<<agg40_blocks, 256>>>(sup16, rowp, edges, b3, out, M);
}